// round 3
// baseline (speedup 1.0000x reference)
#include <cuda_runtime.h>
#include <cuda_bf16.h>
#include <cstdint>
#include <cstddef>

#define DIM 4096
#define NELEM (DIM * DIM)

// ---------------- device scratch (no allocs allowed) ----------------
__device__ float g_pmin[5120];          // [0,1024) x partials, [1024,5120) w partials
__device__ float g_pmax[5120];
__device__ float g_wrsum[DIM];
__device__ float g_scalars[8];          // 0 zero_act, 1 scale_act, 2 zero_w, 3 scale_w, 4 sa*sw, 5 za+4sa
__device__ int8_t g_xq[NELEM];
__device__ int8_t g_wq[NELEM];

// ---------------- helpers ----------------
__device__ __forceinline__ uint32_t smem_u32(const void* p) {
    uint32_t a;
    asm("{ .reg .u64 t; cvta.to.shared.u64 t, %1; cvt.u32.u64 %0, t; }" : "=r"(a) : "l"(p));
    return a;
}
__device__ __forceinline__ void cp16(uint32_t s, const void* g) {
    asm volatile("cp.async.cg.shared.global [%0], [%1], 16;" :: "r"(s), "l"(g));
}
__device__ __forceinline__ void ldsm_x4(uint32_t* r, uint32_t addr) {
    asm volatile("ldmatrix.sync.aligned.m8n8.x4.shared.b16 {%0,%1,%2,%3}, [%4];"
                 : "=r"(r[0]), "=r"(r[1]), "=r"(r[2]), "=r"(r[3]) : "r"(addr));
}
__device__ __forceinline__ void imma(int* c, const uint32_t* a, const uint32_t* b) {
    asm volatile(
        "mma.sync.aligned.m16n8k32.row.col.s32.s8.s8.s32 "
        "{%0,%1,%2,%3}, {%4,%5,%6,%7}, {%8,%9}, {%0,%1,%2,%3};"
        : "+r"(c[0]), "+r"(c[1]), "+r"(c[2]), "+r"(c[3])
        : "r"(a[0]), "r"(a[1]), "r"(a[2]), "r"(a[3]), "r"(b[0]), "r"(b[1]));
}

// ---------------- pass 1: x min/max partials ----------------
__global__ void __launch_bounds__(256) k_reduce_x(const float* __restrict__ x) {
    const float4* x4 = reinterpret_cast<const float4*>(x);
    int t = blockIdx.x * 256 + threadIdx.x;
    float mn = 3.4e38f, mx = -3.4e38f;
#pragma unroll
    for (int i = 0; i < 16; i++) {
        float4 v = x4[t + i * (1024 * 256)];
        mn = fminf(mn, fminf(fminf(v.x, v.y), fminf(v.z, v.w)));
        mx = fmaxf(mx, fmaxf(fmaxf(v.x, v.y), fmaxf(v.z, v.w)));
    }
#pragma unroll
    for (int o = 16; o > 0; o >>= 1) {
        mn = fminf(mn, __shfl_xor_sync(0xffffffffu, mn, o));
        mx = fmaxf(mx, __shfl_xor_sync(0xffffffffu, mx, o));
    }
    __shared__ float smn[8], smx[8];
    int w = threadIdx.x >> 5;
    if ((threadIdx.x & 31) == 0) { smn[w] = mn; smx[w] = mx; }
    __syncthreads();
    if (threadIdx.x == 0) {
        for (int i = 1; i < 8; i++) { mn = fminf(mn, smn[i]); mx = fmaxf(mx, smx[i]); }
        g_pmin[blockIdx.x] = mn;
        g_pmax[blockIdx.x] = mx;
    }
}

// ---------------- pass 2: weight row sums + min/max partials ----------------
__global__ void __launch_bounds__(128) k_row_w(const float* __restrict__ wt) {
    int row = blockIdx.x;
    const float4* w4 = reinterpret_cast<const float4*>(wt + (size_t)row * DIM);
    float s = 0.f, mn = 3.4e38f, mx = -3.4e38f;
#pragma unroll
    for (int i = 0; i < 8; i++) {
        float4 v = w4[threadIdx.x + i * 128];
        s += (v.x + v.y) + (v.z + v.w);
        mn = fminf(mn, fminf(fminf(v.x, v.y), fminf(v.z, v.w)));
        mx = fmaxf(mx, fmaxf(fmaxf(v.x, v.y), fmaxf(v.z, v.w)));
    }
#pragma unroll
    for (int o = 16; o > 0; o >>= 1) {
        s += __shfl_xor_sync(0xffffffffu, s, o);
        mn = fminf(mn, __shfl_xor_sync(0xffffffffu, mn, o));
        mx = fmaxf(mx, __shfl_xor_sync(0xffffffffu, mx, o));
    }
    __shared__ float ss[4], smn[4], smx[4];
    int w = threadIdx.x >> 5;
    if ((threadIdx.x & 31) == 0) { ss[w] = s; smn[w] = mn; smx[w] = mx; }
    __syncthreads();
    if (threadIdx.x == 0) {
        for (int i = 1; i < 4; i++) {
            s += ss[i]; mn = fminf(mn, smn[i]); mx = fmaxf(mx, smx[i]);
        }
        g_wrsum[row] = s;
        g_pmin[1024 + row] = mn;
        g_pmax[1024 + row] = mx;
    }
}

// ---------------- pass 3: finalize scalars ----------------
__global__ void __launch_bounds__(256) k_scalars() {
    int tid = threadIdx.x;
    float xmn = 3.4e38f, xmx = -3.4e38f, wmn = 3.4e38f, wmx = -3.4e38f;
    for (int i = tid; i < 1024; i += 256) {
        xmn = fminf(xmn, g_pmin[i]); xmx = fmaxf(xmx, g_pmax[i]);
    }
    for (int i = tid; i < 4096; i += 256) {
        wmn = fminf(wmn, g_pmin[1024 + i]); wmx = fmaxf(wmx, g_pmax[1024 + i]);
    }
#pragma unroll
    for (int o = 16; o > 0; o >>= 1) {
        xmn = fminf(xmn, __shfl_xor_sync(0xffffffffu, xmn, o));
        xmx = fmaxf(xmx, __shfl_xor_sync(0xffffffffu, xmx, o));
        wmn = fminf(wmn, __shfl_xor_sync(0xffffffffu, wmn, o));
        wmx = fmaxf(wmx, __shfl_xor_sync(0xffffffffu, wmx, o));
    }
    __shared__ float s0[8], s1[8], s2[8], s3[8];
    int w = tid >> 5;
    if ((tid & 31) == 0) { s0[w] = xmn; s1[w] = xmx; s2[w] = wmn; s3[w] = wmx; }
    __syncthreads();
    if (tid == 0) {
        for (int i = 1; i < 8; i++) {
            xmn = fminf(xmn, s0[i]); xmx = fmaxf(xmx, s1[i]);
            wmn = fminf(wmn, s2[i]); wmx = fmaxf(wmx, s3[i]);
        }
        float za = xmn;
        float sa = (xmx - xmn) * 0.125f;   // /(2*HALF_RANGE) = /8 (exact)
        float sw = (wmx - wmn) * 0.125f;
        g_scalars[0] = za;
        g_scalars[1] = sa;
        g_scalars[2] = wmn;
        g_scalars[3] = sw;
        g_scalars[4] = sa * sw;
        g_scalars[5] = za + 4.0f * sa;
    }
}

// ---------------- pass 4: quantize x and w to int8 ----------------
__global__ void __launch_bounds__(256) k_quant(const float* __restrict__ x,
                                               const float* __restrict__ wt) {
    float za = g_scalars[0], sa = g_scalars[1];
    float zw = g_scalars[2], sw = g_scalars[3];
    int t = blockIdx.x * 256 + threadIdx.x;   // 4096*256 = 1,048,576 threads
#pragma unroll
    for (int it = 0; it < 8; it++) {
        int i = t + it * 1048576;             // float4 index in [0, 2*NELEM/4)
        const float4* src;
        int8_t* dst;
        float z, sc;
        int li;
        if (i < NELEM / 4) {
            src = reinterpret_cast<const float4*>(x); dst = g_xq; z = za; sc = sa; li = i;
        } else {
            src = reinterpret_cast<const float4*>(wt); dst = g_wq; z = zw; sc = sw; li = i - NELEM / 4;
        }
        float4 v = src[li];
        int q0 = (int)fminf(fmaxf((v.x - z) / sc - 4.0f, -4.0f), 3.0f);
        int q1 = (int)fminf(fmaxf((v.y - z) / sc - 4.0f, -4.0f), 3.0f);
        int q2 = (int)fminf(fmaxf((v.z - z) / sc - 4.0f, -4.0f), 3.0f);
        int q3 = (int)fminf(fmaxf((v.w - z) / sc - 4.0f, -4.0f), 3.0f);
        uint32_t pk = (uint32_t)(q0 & 0xFF) | ((uint32_t)(q1 & 0xFF) << 8) |
                      ((uint32_t)(q2 & 0xFF) << 16) | ((uint32_t)(q3 & 0xFF) << 24);
        *reinterpret_cast<uint32_t*>(dst + (size_t)li * 4) = pk;
    }
}

// ---------------- pass 5: int8 IMMA GEMM + dequant epilogue ----------------
#define STAGES 3
#define A_BYTES 16384              // 128 rows x 128B
#define STAGE_BYTES 32768          // A tile + B tile
#define GSMEM (STAGES * STAGE_BYTES)
#define NCHUNK (DIM / 128)         // 32
#define NTHREADS 512

__global__ void __launch_bounds__(NTHREADS) k_gemm(const float* __restrict__ bias,
                                                   float* __restrict__ out) {
    extern __shared__ char dsm[];
    uint32_t data = smem_u32(dsm);
    int tid = threadIdx.x;
    int wid = tid >> 5, lid = tid & 31;
    int n0 = blockIdx.x * 128, m0 = blockIdx.y * 128;
    int warpM = wid & 3, warpN = wid >> 2;   // 4 x 4 warps -> warp tile 32m x 32n

    const int8_t* gA = g_xq + (size_t)m0 * DIM;
    const int8_t* gB = g_wq + (size_t)n0 * DIM;

    // cp.async mapping: 1024 16B segments per 16KB tile, 2 per thread per tile.
    uint32_t soff[2];
    const int8_t* pa[2];
    const int8_t* pb[2];
#pragma unroll
    for (int j = 0; j < 2; j++) {
        int seg = tid + j * NTHREADS;
        int row = seg >> 3, c = seg & 7;
        soff[j] = (uint32_t)(row * 128 + ((c ^ (row & 7)) << 4));
        pa[j] = gA + (size_t)row * DIM + c * 16;
        pb[j] = gB + (size_t)row * DIM + c * 16;
    }

    // ldmatrix addressing (s8 fragments via b16 ldmatrix reinterpretation).
    // A (m16k32 tile): t0-7 rows+0..7 k-lo, t8-15 rows+8..15 k-lo,
    //                  t16-23 rows+0..7 k-hi, t24-31 rows+8..15 k-hi.
    uint32_t a_rowoff[2], a_rowx[2];
#pragma unroll
    for (int mt = 0; mt < 2; mt++) {
        int r = warpM * 32 + mt * 16 + ((lid >> 3) & 1) * 8 + (lid & 7);
        a_rowoff[mt] = (uint32_t)(r * 128);
        a_rowx[mt] = (uint32_t)(r & 7);
    }
    int a_khalf = (lid >> 4) & 1;            // col16 = 2k + a_khalf
    // B (two n8k32 frag pairs per x4): t0-7 n+0..7 k-lo, t8-15 n+0..7 k-hi,
    //                                  t16-23 n+8..15 k-lo, t24-31 n+8..15 k-hi.
    uint32_t b_rowoff[2], b_rowx[2];
#pragma unroll
    for (int np = 0; np < 2; np++) {
        int r = warpN * 32 + np * 16 + ((lid >> 4) & 1) * 8 + (lid & 7);
        b_rowoff[np] = (uint32_t)(r * 128);
        b_rowx[np] = (uint32_t)(r & 7);
    }
    int b_khalf = (lid >> 3) & 1;

    int acc[2][4][4];
#pragma unroll
    for (int mt = 0; mt < 2; mt++)
#pragma unroll
        for (int nt = 0; nt < 4; nt++)
#pragma unroll
            for (int c = 0; c < 4; c++) acc[mt][nt][c] = 0;

    // prologue: fill STAGES-1 stages
#pragma unroll
    for (int s = 0; s < STAGES - 1; s++) {
        uint32_t base = data + s * STAGE_BYTES;
        int ko = s * 128;
#pragma unroll
        for (int j = 0; j < 2; j++) cp16(base + soff[j], pa[j] + ko);
#pragma unroll
        for (int j = 0; j < 2; j++) cp16(base + A_BYTES + soff[j], pb[j] + ko);
        asm volatile("cp.async.commit_group;" ::: "memory");
    }

    for (int i = 0; i < NCHUNK; i++) {
        // chunk i was committed STAGES-1 groups back -> complete after this wait
        asm volatile("cp.async.wait_group %0;" :: "n"(STAGES - 2) : "memory");
        __syncthreads();

        // issue loads for chunk i+STAGES-1 into its slot ( == slot of chunk i-1,
        // safe: all warps finished computing it before the barrier above)
        int nj = i + STAGES - 1;
        if (nj < NCHUNK) {
            uint32_t wbase = data + (nj % STAGES) * STAGE_BYTES;
            int ko = nj * 128;
#pragma unroll
            for (int j = 0; j < 2; j++) cp16(wbase + soff[j], pa[j] + ko);
#pragma unroll
            for (int j = 0; j < 2; j++) cp16(wbase + A_BYTES + soff[j], pb[j] + ko);
        }
        asm volatile("cp.async.commit_group;" ::: "memory");

        // compute chunk i
        uint32_t baseA = data + (i % STAGES) * STAGE_BYTES;
        uint32_t baseB = baseA + A_BYTES;
#pragma unroll
        for (int k = 0; k < 4; k++) {
            uint32_t afr[2][4];
#pragma unroll
            for (int mt = 0; mt < 2; mt++) {
                uint32_t col = (uint32_t)(2 * k + a_khalf) ^ a_rowx[mt];
                ldsm_x4(afr[mt], baseA + a_rowoff[mt] + (col << 4));
            }
#pragma unroll
            for (int np = 0; np < 2; np++) {
                uint32_t bfr[4];
                uint32_t col = (uint32_t)(2 * k + b_khalf) ^ b_rowx[np];
                ldsm_x4(bfr, baseB + b_rowoff[np] + (col << 4));
#pragma unroll
                for (int mt = 0; mt < 2; mt++) {
                    imma(acc[mt][np * 2 + 0], afr[mt], bfr + 0);
                    imma(acc[mt][np * 2 + 1], afr[mt], bfr + 2);
                }
            }
        }
    }

    // epilogue: out[m][n] = (acc + bias[n]) * (sa*sw) + (za + 4*sa) * wrsum[m]
    float comb = g_scalars[4];
    float shc  = g_scalars[5];
#pragma unroll
    for (int mt = 0; mt < 2; mt++) {
        int r0 = m0 + warpM * 32 + mt * 16 + (lid >> 2);
        int r1 = r0 + 8;
        float sh0 = shc * g_wrsum[r0];
        float sh1 = shc * g_wrsum[r1];
#pragma unroll
        for (int nt = 0; nt < 4; nt++) {
            int col = n0 + warpN * 32 + nt * 8 + (lid & 3) * 2;
            float b0 = bias[col], b1 = bias[col + 1];
            float2 o0, o1;
            o0.x = ((float)acc[mt][nt][0] + b0) * comb + sh0;
            o0.y = ((float)acc[mt][nt][1] + b1) * comb + sh0;
            o1.x = ((float)acc[mt][nt][2] + b0) * comb + sh1;
            o1.y = ((float)acc[mt][nt][3] + b1) * comb + sh1;
            *reinterpret_cast<float2*>(out + (size_t)r0 * DIM + col) = o0;
            *reinterpret_cast<float2*>(out + (size_t)r1 * DIM + col) = o1;
        }
    }
}

// ---------------- launch ----------------
extern "C" void kernel_launch(void* const* d_in, const int* in_sizes, int n_in,
                              void* d_out, int out_size) {
    const float* x    = (const float*)d_in[0];
    const float* wt   = (const float*)d_in[1];
    const float* bias = (const float*)d_in[2];
    float* out = (float*)d_out;

    cudaFuncSetAttribute(k_gemm, cudaFuncAttributeMaxDynamicSharedMemorySize, GSMEM);

    k_reduce_x<<<1024, 256>>>(x);
    k_row_w<<<4096, 128>>>(wt);
    k_scalars<<<1, 256>>>();
    k_quant<<<4096, 256>>>(x, wt);
    dim3 grid(DIM / 128, DIM / 128);
    k_gemm<<<grid, NTHREADS, GSMEM>>>(bias, out);
}

// round 5
// speedup vs baseline: 1.4594x; 1.4594x over previous
#include <cuda_runtime.h>
#include <cuda_bf16.h>
#include <cstdint>
#include <cstddef>

#define DIM 4096
#define NELEM (DIM * DIM)

// ---------------- device scratch (no allocs allowed) ----------------
__device__ float g_pmin[5120];          // [0,1024) x partials, [1024,5120) w partials
__device__ float g_pmax[5120];
__device__ float g_wrsum[DIM];
__device__ float g_scalars[8];          // 0 zero_act, 1 scale_act, 2 zero_w, 3 scale_w, 4 sa*sw, 5 za+4sa
__device__ int8_t g_xq[NELEM];
__device__ int8_t g_wq[NELEM];

// ---------------- helpers ----------------
__device__ __forceinline__ uint32_t smem_u32(const void* p) {
    uint32_t a;
    asm("{ .reg .u64 t; cvta.to.shared.u64 t, %1; cvt.u32.u64 %0, t; }" : "=r"(a) : "l"(p));
    return a;
}
__device__ __forceinline__ void cp16(uint32_t s, const void* g) {
    asm volatile("cp.async.cg.shared.global [%0], [%1], 16;" :: "r"(s), "l"(g));
}
__device__ __forceinline__ void ldsm_x4(uint32_t* r, uint32_t addr) {
    asm volatile("ldmatrix.sync.aligned.m8n8.x4.shared.b16 {%0,%1,%2,%3}, [%4];"
                 : "=r"(r[0]), "=r"(r[1]), "=r"(r[2]), "=r"(r[3]) : "r"(addr));
}
__device__ __forceinline__ void imma(int* c, const uint32_t* a, const uint32_t* b) {
    asm volatile(
        "mma.sync.aligned.m16n8k32.row.col.s32.s8.s8.s32 "
        "{%0,%1,%2,%3}, {%4,%5,%6,%7}, {%8,%9}, {%0,%1,%2,%3};"
        : "+r"(c[0]), "+r"(c[1]), "+r"(c[2]), "+r"(c[3])
        : "r"(a[0]), "r"(a[1]), "r"(a[2]), "r"(a[3]), "r"(b[0]), "r"(b[1]));
}
__device__ __forceinline__ int lds32(uint32_t addr) {
    int v;
    asm("ld.shared.b32 %0, [%1];" : "=r"(v) : "r"(addr));
    return v;
}

// ---------------- pass 1: x min/max partials ----------------
__global__ void __launch_bounds__(256) k_reduce_x(const float* __restrict__ x) {
    const float4* x4 = reinterpret_cast<const float4*>(x);
    int t = blockIdx.x * 256 + threadIdx.x;
    float mn = 3.4e38f, mx = -3.4e38f;
#pragma unroll
    for (int i = 0; i < 16; i++) {
        float4 v = x4[t + i * (1024 * 256)];
        mn = fminf(mn, fminf(fminf(v.x, v.y), fminf(v.z, v.w)));
        mx = fmaxf(mx, fmaxf(fmaxf(v.x, v.y), fmaxf(v.z, v.w)));
    }
#pragma unroll
    for (int o = 16; o > 0; o >>= 1) {
        mn = fminf(mn, __shfl_xor_sync(0xffffffffu, mn, o));
        mx = fmaxf(mx, __shfl_xor_sync(0xffffffffu, mx, o));
    }
    __shared__ float smn[8], smx[8];
    int w = threadIdx.x >> 5;
    if ((threadIdx.x & 31) == 0) { smn[w] = mn; smx[w] = mx; }
    __syncthreads();
    if (threadIdx.x == 0) {
        for (int i = 1; i < 8; i++) { mn = fminf(mn, smn[i]); mx = fmaxf(mx, smx[i]); }
        g_pmin[blockIdx.x] = mn;
        g_pmax[blockIdx.x] = mx;
    }
}

// ---------------- pass 2: weight row sums + min/max partials ----------------
__global__ void __launch_bounds__(128) k_row_w(const float* __restrict__ wt) {
    int row = blockIdx.x;
    const float4* w4 = reinterpret_cast<const float4*>(wt + (size_t)row * DIM);
    float s = 0.f, mn = 3.4e38f, mx = -3.4e38f;
#pragma unroll
    for (int i = 0; i < 8; i++) {
        float4 v = w4[threadIdx.x + i * 128];
        s += (v.x + v.y) + (v.z + v.w);
        mn = fminf(mn, fminf(fminf(v.x, v.y), fminf(v.z, v.w)));
        mx = fmaxf(mx, fmaxf(fmaxf(v.x, v.y), fmaxf(v.z, v.w)));
    }
#pragma unroll
    for (int o = 16; o > 0; o >>= 1) {
        s += __shfl_xor_sync(0xffffffffu, s, o);
        mn = fminf(mn, __shfl_xor_sync(0xffffffffu, mn, o));
        mx = fmaxf(mx, __shfl_xor_sync(0xffffffffu, mx, o));
    }
    __shared__ float ss[4], smn[4], smx[4];
    int w = threadIdx.x >> 5;
    if ((threadIdx.x & 31) == 0) { ss[w] = s; smn[w] = mn; smx[w] = mx; }
    __syncthreads();
    if (threadIdx.x == 0) {
        for (int i = 1; i < 4; i++) {
            s += ss[i]; mn = fminf(mn, smn[i]); mx = fmaxf(mx, smx[i]);
        }
        g_wrsum[row] = s;
        g_pmin[1024 + row] = mn;
        g_pmax[1024 + row] = mx;
    }
}

// ---------------- pass 3: finalize scalars ----------------
__global__ void __launch_bounds__(256) k_scalars() {
    int tid = threadIdx.x;
    float xmn = 3.4e38f, xmx = -3.4e38f, wmn = 3.4e38f, wmx = -3.4e38f;
    for (int i = tid; i < 1024; i += 256) {
        xmn = fminf(xmn, g_pmin[i]); xmx = fmaxf(xmx, g_pmax[i]);
    }
    for (int i = tid; i < 4096; i += 256) {
        wmn = fminf(wmn, g_pmin[1024 + i]); wmx = fmaxf(wmx, g_pmax[1024 + i]);
    }
#pragma unroll
    for (int o = 16; o > 0; o >>= 1) {
        xmn = fminf(xmn, __shfl_xor_sync(0xffffffffu, xmn, o));
        xmx = fmaxf(xmx, __shfl_xor_sync(0xffffffffu, xmx, o));
        wmn = fminf(wmn, __shfl_xor_sync(0xffffffffu, wmn, o));
        wmx = fmaxf(wmx, __shfl_xor_sync(0xffffffffu, wmx, o));
    }
    __shared__ float s0[8], s1[8], s2[8], s3[8];
    int w = tid >> 5;
    if ((tid & 31) == 0) { s0[w] = xmn; s1[w] = xmx; s2[w] = wmn; s3[w] = wmx; }
    __syncthreads();
    if (tid == 0) {
        for (int i = 1; i < 8; i++) {
            xmn = fminf(xmn, s0[i]); xmx = fmaxf(xmx, s1[i]);
            wmn = fminf(wmn, s2[i]); wmx = fmaxf(wmx, s3[i]);
        }
        float za = xmn;
        float sa = (xmx - xmn) * 0.125f;   // /(2*HALF_RANGE) = /8 (exact)
        float sw = (wmx - wmn) * 0.125f;
        g_scalars[0] = za;
        g_scalars[1] = sa;
        g_scalars[2] = wmn;
        g_scalars[3] = sw;
        g_scalars[4] = sa * sw;
        g_scalars[5] = za + 4.0f * sa;
    }
}

// ---------------- pass 4: quantize x and w to int8 ----------------
__global__ void __launch_bounds__(256) k_quant(const float* __restrict__ x,
                                               const float* __restrict__ wt) {
    float za = g_scalars[0], sa = g_scalars[1];
    float zw = g_scalars[2], sw = g_scalars[3];
    int t = blockIdx.x * 256 + threadIdx.x;   // 4096*256 = 1,048,576 threads
#pragma unroll
    for (int it = 0; it < 8; it++) {
        int i = t + it * 1048576;             // float4 index in [0, 2*NELEM/4)
        const float4* src;
        int8_t* dst;
        float z, sc;
        int li;
        if (i < NELEM / 4) {
            src = reinterpret_cast<const float4*>(x); dst = g_xq; z = za; sc = sa; li = i;
        } else {
            src = reinterpret_cast<const float4*>(wt); dst = g_wq; z = zw; sc = sw; li = i - NELEM / 4;
        }
        float4 v = src[li];
        int q0 = (int)fminf(fmaxf((v.x - z) / sc - 4.0f, -4.0f), 3.0f);
        int q1 = (int)fminf(fmaxf((v.y - z) / sc - 4.0f, -4.0f), 3.0f);
        int q2 = (int)fminf(fmaxf((v.z - z) / sc - 4.0f, -4.0f), 3.0f);
        int q3 = (int)fminf(fmaxf((v.w - z) / sc - 4.0f, -4.0f), 3.0f);
        uint32_t pk = (uint32_t)(q0 & 0xFF) | ((uint32_t)(q1 & 0xFF) << 8) |
                      ((uint32_t)(q2 & 0xFF) << 16) | ((uint32_t)(q3 & 0xFF) << 24);
        *reinterpret_cast<uint32_t*>(dst + (size_t)li * 4) = pk;
    }
}

// ---------------- pass 5: hybrid IMMA + DP4A GEMM + dequant epilogue ----------------
// 128x128 CTA tile, K chunks of 128. Warps 0-7 (IMMA, tensor pipe) take k[0,64)
// of each chunk; warps 8-15 (DP4A, fma pipe) take k[64,128). Both pipes run
// concurrently at ~256 MACs/cyc/SM each. Partials combined via smem at the end.
#define STAGES 3
#define A_BYTES 16384              // 128 rows x 128B
#define STAGE_BYTES 32768          // A tile + B tile
#define GSMEM (STAGES * STAGE_BYTES)
#define NCHUNK (DIM / 128)         // 32
#define NTHREADS 512

__global__ void __launch_bounds__(NTHREADS) k_gemm(const float* __restrict__ bias,
                                                   float* __restrict__ out) {
    extern __shared__ char dsm[];
    uint32_t data = smem_u32(dsm);
    int tid = threadIdx.x;
    int wid = tid >> 5, lid = tid & 31;
    int n0 = blockIdx.x * 128, m0 = blockIdx.y * 128;
    bool is_imma = (wid < 8);
    int w8 = wid & 7;
    int warpM = w8 & 3, warpN = w8 >> 2;   // both roles: 4x2 warps, 32m x 64n tile

    const int8_t* gA = g_xq + (size_t)m0 * DIM;
    const int8_t* gB = g_wq + (size_t)n0 * DIM;

    // cp.async mapping: 1024 16B segments per 16KB tile, 2 per thread per tile.
    uint32_t soff[2];
    const int8_t* pa[2];
    const int8_t* pb[2];
#pragma unroll
    for (int j = 0; j < 2; j++) {
        int seg = tid + j * NTHREADS;
        int row = seg >> 3, c = seg & 7;
        soff[j] = (uint32_t)(row * 128 + ((c ^ (row & 7)) << 4));
        pa[j] = gA + (size_t)row * DIM + c * 16;
        pb[j] = gB + (size_t)row * DIM + c * 16;
    }

    // IMMA ldmatrix addressing (s8 fragments via b16 ldmatrix reinterpretation).
    uint32_t a_rowoff[2], a_rowx[2];
#pragma unroll
    for (int mt = 0; mt < 2; mt++) {
        int r = warpM * 32 + mt * 16 + ((lid >> 3) & 1) * 8 + (lid & 7);
        a_rowoff[mt] = (uint32_t)(r * 128);
        a_rowx[mt] = (uint32_t)(r & 7);
    }
    int a_khalf = (lid >> 4) & 1;
    uint32_t b_rowoff[4], b_rowx[4];
#pragma unroll
    for (int np = 0; np < 4; np++) {
        int r = warpN * 64 + np * 16 + ((lid >> 4) & 1) * 8 + (lid & 7);
        b_rowoff[np] = (uint32_t)(r * 128);
        b_rowx[np] = (uint32_t)(r & 7);
    }
    int b_khalf = (lid >> 3) & 1;

    // DP4A mapping: rows warpM*32 + a + 4i (a=lid&3), cols warpN*64 + g + 8j (g=lid>>2).
    // row&7 distinct across a-lanes, col&7 distinct across g-lanes -> conflict-free LDS.
    int la = lid & 3, lg = lid >> 2;

    int acc[64];
#pragma unroll
    for (int c = 0; c < 64; c++) acc[c] = 0;

    // prologue: fill STAGES-1 stages
#pragma unroll
    for (int s = 0; s < STAGES - 1; s++) {
        uint32_t base = data + s * STAGE_BYTES;
        int ko = s * 128;
#pragma unroll
        for (int j = 0; j < 2; j++) cp16(base + soff[j], pa[j] + ko);
#pragma unroll
        for (int j = 0; j < 2; j++) cp16(base + A_BYTES + soff[j], pb[j] + ko);
        asm volatile("cp.async.commit_group;" ::: "memory");
    }

    for (int i = 0; i < NCHUNK; i++) {
        asm volatile("cp.async.wait_group %0;" :: "n"(STAGES - 2) : "memory");
        __syncthreads();

        int nj = i + STAGES - 1;
        if (nj < NCHUNK) {
            uint32_t wbase = data + (nj % STAGES) * STAGE_BYTES;
            int ko = nj * 128;
#pragma unroll
            for (int j = 0; j < 2; j++) cp16(wbase + soff[j], pa[j] + ko);
#pragma unroll
            for (int j = 0; j < 2; j++) cp16(wbase + A_BYTES + soff[j], pb[j] + ko);
        }
        asm volatile("cp.async.commit_group;" ::: "memory");

        uint32_t baseA = data + (i % STAGES) * STAGE_BYTES;
        uint32_t baseB = baseA + A_BYTES;

        if (is_imma) {
            // k bytes [0,64): 2 k-steps of m16n8k32
#pragma unroll
            for (int k = 0; k < 2; k++) {
                uint32_t afr[2][4];
#pragma unroll
                for (int mt = 0; mt < 2; mt++) {
                    uint32_t col = (uint32_t)(2 * k + a_khalf) ^ a_rowx[mt];
                    ldsm_x4(afr[mt], baseA + a_rowoff[mt] + (col << 4));
                }
#pragma unroll
                for (int np = 0; np < 4; np++) {
                    uint32_t bfr[4];
                    uint32_t col = (uint32_t)(2 * k + b_khalf) ^ b_rowx[np];
                    ldsm_x4(bfr, baseB + b_rowoff[np] + (col << 4));
#pragma unroll
                    for (int mt = 0; mt < 2; mt++) {
                        imma(&acc[(mt * 8 + np * 2 + 0) * 4], afr[mt], bfr + 0);
                        imma(&acc[(mt * 8 + np * 2 + 1) * 4], afr[mt], bfr + 2);
                    }
                }
            }
        } else {
            // k bytes [64,128): 16 k-quads of dp4a
#pragma unroll 4
            for (int kq = 16; kq < 32; kq++) {
                uint32_t c16 = (uint32_t)(kq >> 2);
                uint32_t lo = (uint32_t)((kq & 3) * 4);
                int areg[8], breg[8];
#pragma unroll
                for (int ii = 0; ii < 8; ii++) {
                    int r = warpM * 32 + la + 4 * ii;
                    areg[ii] = lds32(baseA + (uint32_t)(r * 128) +
                                     ((c16 ^ (uint32_t)(r & 7)) << 4) + lo);
                }
#pragma unroll
                for (int jj = 0; jj < 8; jj++) {
                    int r = warpN * 64 + lg + 8 * jj;
                    breg[jj] = lds32(baseB + (uint32_t)(r * 128) +
                                     ((c16 ^ (uint32_t)(r & 7)) << 4) + lo);
                }
#pragma unroll
                for (int ii = 0; ii < 8; ii++)
#pragma unroll
                    for (int jj = 0; jj < 8; jj++)
                        acc[ii * 8 + jj] = __dp4a(areg[ii], breg[jj], acc[ii * 8 + jj]);
            }
        }
    }

    // combine dp4a partials into imma warps, then dequant epilogue
    __syncthreads();
    int* buf = reinterpret_cast<int*>(dsm);    // 64KB, reuses pipeline stages
    if (!is_imma) {
#pragma unroll
        for (int ii = 0; ii < 8; ii++) {
            int rl = warpM * 32 + la + 4 * ii;
#pragma unroll
            for (int jj = 0; jj < 8; jj++)
                buf[rl * 128 + warpN * 64 + lg + 8 * jj] = acc[ii * 8 + jj];
        }
    }
    __syncthreads();

    if (is_imma) {
        float comb = g_scalars[4];
        float shc  = g_scalars[5];
#pragma unroll
        for (int mt = 0; mt < 2; mt++) {
            int r0l = warpM * 32 + mt * 16 + (lid >> 2);
            int r1l = r0l + 8;
            int r0 = m0 + r0l, r1 = m0 + r1l;
            float sh0 = shc * g_wrsum[r0];
            float sh1 = shc * g_wrsum[r1];
#pragma unroll
            for (int nt = 0; nt < 8; nt++) {
                int cl = warpN * 64 + nt * 8 + (lid & 3) * 2;
                int col = n0 + cl;
                float b0 = bias[col], b1 = bias[col + 1];
                int2 p0 = *reinterpret_cast<int2*>(buf + r0l * 128 + cl);
                int2 p1 = *reinterpret_cast<int2*>(buf + r1l * 128 + cl);
                const int* ac = &acc[(mt * 8 + nt) * 4];
                float2 o0, o1;
                o0.x = ((float)(ac[0] + p0.x) + b0) * comb + sh0;
                o0.y = ((float)(ac[1] + p0.y) + b1) * comb + sh0;
                o1.x = ((float)(ac[2] + p1.x) + b0) * comb + sh1;
                o1.y = ((float)(ac[3] + p1.y) + b1) * comb + sh1;
                *reinterpret_cast<float2*>(out + (size_t)r0 * DIM + col) = o0;
                *reinterpret_cast<float2*>(out + (size_t)r1 * DIM + col) = o1;
            }
        }
    }
}

// ---------------- launch ----------------
extern "C" void kernel_launch(void* const* d_in, const int* in_sizes, int n_in,
                              void* d_out, int out_size) {
    const float* x    = (const float*)d_in[0];
    const float* wt   = (const float*)d_in[1];
    const float* bias = (const float*)d_in[2];
    float* out = (float*)d_out;

    cudaFuncSetAttribute(k_gemm, cudaFuncAttributeMaxDynamicSharedMemorySize, GSMEM);

    k_reduce_x<<<1024, 256>>>(x);
    k_row_w<<<4096, 128>>>(wt);
    k_scalars<<<1, 256>>>();
    k_quant<<<4096, 256>>>(x, wt);
    dim3 grid(DIM / 128, DIM / 128);
    k_gemm<<<grid, NTHREADS, GSMEM>>>(bias, out);
}

// round 6
// speedup vs baseline: 1.4735x; 1.0097x over previous
#include <cuda_runtime.h>
#include <cuda_bf16.h>
#include <cstdint>
#include <cstddef>

#define DIM 4096
#define NELEM (DIM * DIM)

// ---------------- device scratch (no allocs allowed) ----------------
__device__ float g_pmin[5120];          // [0,1024) x partials, [1024,5120) w partials
__device__ float g_pmax[5120];
__device__ float g_wrsum[DIM];
__device__ float g_scalars[8];          // 0 zero_act, 1 scale_act, 2 zero_w, 3 scale_w, 4 sa*sw, 5 za+4sa
__device__ int8_t g_xq[NELEM];
__device__ int8_t g_wq[NELEM];

// ---------------- helpers ----------------
__device__ __forceinline__ uint32_t smem_u32(const void* p) {
    uint32_t a;
    asm("{ .reg .u64 t; cvta.to.shared.u64 t, %1; cvt.u32.u64 %0, t; }" : "=r"(a) : "l"(p));
    return a;
}
__device__ __forceinline__ void cp16(uint32_t s, const void* g) {
    asm volatile("cp.async.cg.shared.global [%0], [%1], 16;" :: "r"(s), "l"(g));
}
__device__ __forceinline__ void ldsm_x4(uint32_t* r, uint32_t addr) {
    asm volatile("ldmatrix.sync.aligned.m8n8.x4.shared.b16 {%0,%1,%2,%3}, [%4];"
                 : "=r"(r[0]), "=r"(r[1]), "=r"(r[2]), "=r"(r[3]) : "r"(addr));
}
__device__ __forceinline__ void imma(int* c, const uint32_t* a, const uint32_t* b) {
    asm volatile(
        "mma.sync.aligned.m16n8k32.row.col.s32.s8.s8.s32 "
        "{%0,%1,%2,%3}, {%4,%5,%6,%7}, {%8,%9}, {%0,%1,%2,%3};"
        : "+r"(c[0]), "+r"(c[1]), "+r"(c[2]), "+r"(c[3])
        : "r"(a[0]), "r"(a[1]), "r"(a[2]), "r"(a[3]), "r"(b[0]), "r"(b[1]));
}
__device__ __forceinline__ int4 lds128v(uint32_t addr) {
    int4 v;
    asm("ld.shared.v4.b32 {%0,%1,%2,%3}, [%4];"
        : "=r"(v.x), "=r"(v.y), "=r"(v.z), "=r"(v.w) : "r"(addr));
    return v;
}

// ---------------- pass 1: x min/max partials ----------------
__global__ void __launch_bounds__(256) k_reduce_x(const float* __restrict__ x) {
    const float4* x4 = reinterpret_cast<const float4*>(x);
    int t = blockIdx.x * 256 + threadIdx.x;
    float mn = 3.4e38f, mx = -3.4e38f;
#pragma unroll
    for (int i = 0; i < 16; i++) {
        float4 v = x4[t + i * (1024 * 256)];
        mn = fminf(mn, fminf(fminf(v.x, v.y), fminf(v.z, v.w)));
        mx = fmaxf(mx, fmaxf(fmaxf(v.x, v.y), fmaxf(v.z, v.w)));
    }
#pragma unroll
    for (int o = 16; o > 0; o >>= 1) {
        mn = fminf(mn, __shfl_xor_sync(0xffffffffu, mn, o));
        mx = fmaxf(mx, __shfl_xor_sync(0xffffffffu, mx, o));
    }
    __shared__ float smn[8], smx[8];
    int w = threadIdx.x >> 5;
    if ((threadIdx.x & 31) == 0) { smn[w] = mn; smx[w] = mx; }
    __syncthreads();
    if (threadIdx.x == 0) {
        for (int i = 1; i < 8; i++) { mn = fminf(mn, smn[i]); mx = fmaxf(mx, smx[i]); }
        g_pmin[blockIdx.x] = mn;
        g_pmax[blockIdx.x] = mx;
    }
}

// ---------------- pass 2: weight row sums + min/max partials ----------------
__global__ void __launch_bounds__(128) k_row_w(const float* __restrict__ wt) {
    int row = blockIdx.x;
    const float4* w4 = reinterpret_cast<const float4*>(wt + (size_t)row * DIM);
    float s = 0.f, mn = 3.4e38f, mx = -3.4e38f;
#pragma unroll
    for (int i = 0; i < 8; i++) {
        float4 v = w4[threadIdx.x + i * 128];
        s += (v.x + v.y) + (v.z + v.w);
        mn = fminf(mn, fminf(fminf(v.x, v.y), fminf(v.z, v.w)));
        mx = fmaxf(mx, fmaxf(fmaxf(v.x, v.y), fmaxf(v.z, v.w)));
    }
#pragma unroll
    for (int o = 16; o > 0; o >>= 1) {
        s += __shfl_xor_sync(0xffffffffu, s, o);
        mn = fminf(mn, __shfl_xor_sync(0xffffffffu, mn, o));
        mx = fmaxf(mx, __shfl_xor_sync(0xffffffffu, mx, o));
    }
    __shared__ float ss[4], smn[4], smx[4];
    int w = threadIdx.x >> 5;
    if ((threadIdx.x & 31) == 0) { ss[w] = s; smn[w] = mn; smx[w] = mx; }
    __syncthreads();
    if (threadIdx.x == 0) {
        for (int i = 1; i < 4; i++) {
            s += ss[i]; mn = fminf(mn, smn[i]); mx = fmaxf(mx, smx[i]);
        }
        g_wrsum[row] = s;
        g_pmin[1024 + row] = mn;
        g_pmax[1024 + row] = mx;
    }
}

// ---------------- pass 3: finalize scalars ----------------
__global__ void __launch_bounds__(256) k_scalars() {
    int tid = threadIdx.x;
    float xmn = 3.4e38f, xmx = -3.4e38f, wmn = 3.4e38f, wmx = -3.4e38f;
    for (int i = tid; i < 1024; i += 256) {
        xmn = fminf(xmn, g_pmin[i]); xmx = fmaxf(xmx, g_pmax[i]);
    }
    for (int i = tid; i < 4096; i += 256) {
        wmn = fminf(wmn, g_pmin[1024 + i]); wmx = fmaxf(wmx, g_pmax[1024 + i]);
    }
#pragma unroll
    for (int o = 16; o > 0; o >>= 1) {
        xmn = fminf(xmn, __shfl_xor_sync(0xffffffffu, xmn, o));
        xmx = fmaxf(xmx, __shfl_xor_sync(0xffffffffu, xmx, o));
        wmn = fminf(wmn, __shfl_xor_sync(0xffffffffu, wmn, o));
        wmx = fmaxf(wmx, __shfl_xor_sync(0xffffffffu, wmx, o));
    }
    __shared__ float s0[8], s1[8], s2[8], s3[8];
    int w = tid >> 5;
    if ((tid & 31) == 0) { s0[w] = xmn; s1[w] = xmx; s2[w] = wmn; s3[w] = wmx; }
    __syncthreads();
    if (tid == 0) {
        for (int i = 1; i < 8; i++) {
            xmn = fminf(xmn, s0[i]); xmx = fmaxf(xmx, s1[i]);
            wmn = fminf(wmn, s2[i]); wmx = fmaxf(wmx, s3[i]);
        }
        float za = xmn;
        float sa = (xmx - xmn) * 0.125f;   // /(2*HALF_RANGE) = /8 (exact)
        float sw = (wmx - wmn) * 0.125f;
        g_scalars[0] = za;
        g_scalars[1] = sa;
        g_scalars[2] = wmn;
        g_scalars[3] = sw;
        g_scalars[4] = sa * sw;
        g_scalars[5] = za + 4.0f * sa;
    }
}

// ---------------- pass 4: quantize x and w to int8 ----------------
__global__ void __launch_bounds__(256) k_quant(const float* __restrict__ x,
                                               const float* __restrict__ wt) {
    float za = g_scalars[0], sa = g_scalars[1];
    float zw = g_scalars[2], sw = g_scalars[3];
    int t = blockIdx.x * 256 + threadIdx.x;   // 4096*256 = 1,048,576 threads
#pragma unroll
    for (int it = 0; it < 8; it++) {
        int i = t + it * 1048576;             // float4 index in [0, 2*NELEM/4)
        const float4* src;
        int8_t* dst;
        float z, sc;
        int li;
        if (i < NELEM / 4) {
            src = reinterpret_cast<const float4*>(x); dst = g_xq; z = za; sc = sa; li = i;
        } else {
            src = reinterpret_cast<const float4*>(wt); dst = g_wq; z = zw; sc = sw; li = i - NELEM / 4;
        }
        float4 v = src[li];
        int q0 = (int)fminf(fmaxf((v.x - z) / sc - 4.0f, -4.0f), 3.0f);
        int q1 = (int)fminf(fmaxf((v.y - z) / sc - 4.0f, -4.0f), 3.0f);
        int q2 = (int)fminf(fmaxf((v.z - z) / sc - 4.0f, -4.0f), 3.0f);
        int q3 = (int)fminf(fmaxf((v.w - z) / sc - 4.0f, -4.0f), 3.0f);
        uint32_t pk = (uint32_t)(q0 & 0xFF) | ((uint32_t)(q1 & 0xFF) << 8) |
                      ((uint32_t)(q2 & 0xFF) << 16) | ((uint32_t)(q3 & 0xFF) << 24);
        *reinterpret_cast<uint32_t*>(dst + (size_t)li * 4) = pk;
    }
}

// ---------------- pass 5: hybrid IMMA + DP4A GEMM + dequant epilogue ----------------
// 128x128 CTA tile, K chunks of 128. Warps 0-7 (IMMA, tensor pipe) take k[0,64)
// of each chunk; warps 8-15 (DP4A, fma pipe) take k[64,128). Both pipes run
// concurrently. DP4A operands fetched via lds128 (one 16B swizzle column = 4
// k-quads), swizzle XOR hoisted per column-block. Partials combined via smem.
#define STAGES 3
#define A_BYTES 16384              // 128 rows x 128B
#define STAGE_BYTES 32768          // A tile + B tile
#define GSMEM (STAGES * STAGE_BYTES)
#define NCHUNK (DIM / 128)         // 32
#define NTHREADS 512

__global__ void __launch_bounds__(NTHREADS) k_gemm(const float* __restrict__ bias,
                                                   float* __restrict__ out) {
    extern __shared__ char dsm[];
    uint32_t data = smem_u32(dsm);
    int tid = threadIdx.x;
    int wid = tid >> 5, lid = tid & 31;
    int n0 = blockIdx.x * 128, m0 = blockIdx.y * 128;
    bool is_imma = (wid < 8);
    int w8 = wid & 7;
    int warpM = w8 & 3, warpN = w8 >> 2;   // both roles: 4x2 warps, 32m x 64n tile

    const int8_t* gA = g_xq + (size_t)m0 * DIM;
    const int8_t* gB = g_wq + (size_t)n0 * DIM;

    // cp.async mapping: 1024 16B segments per 16KB tile, 2 per thread per tile.
    uint32_t soff[2];
    uint32_t goff[2];
#pragma unroll
    for (int j = 0; j < 2; j++) {
        int seg = tid + j * NTHREADS;
        int row = seg >> 3, c = seg & 7;
        soff[j] = (uint32_t)(row * 128 + ((c ^ (row & 7)) << 4));
        goff[j] = (uint32_t)(row * DIM + c * 16);
    }

    // IMMA ldmatrix addressing (s8 fragments via b16 ldmatrix reinterpretation).
    uint32_t a_rowoff[2], a_rowx[2];
#pragma unroll
    for (int mt = 0; mt < 2; mt++) {
        int r = warpM * 32 + mt * 16 + ((lid >> 3) & 1) * 8 + (lid & 7);
        a_rowoff[mt] = (uint32_t)(r * 128);
        a_rowx[mt] = (uint32_t)(r & 7);
    }
    int a_khalf = (lid >> 4) & 1;
    uint32_t b_rowoff[4], b_rowx[4];
#pragma unroll
    for (int np = 0; np < 4; np++) {
        int r = warpN * 64 + np * 16 + ((lid >> 4) & 1) * 8 + (lid & 7);
        b_rowoff[np] = (uint32_t)(r * 128);
        b_rowx[np] = (uint32_t)(r & 7);
    }
    int b_khalf = (lid >> 3) & 1;

    // DP4A mapping: rows warpM*32 + la + 4*ii (la=lid&3), cols warpN*64 + lg + 8*jj
    // (lg=lid>>2). row&7 distinct across la-lanes, col&7 distinct across lg-lanes.
    int la = lid & 3, lg = lid >> 2;

    int acc[64];
#pragma unroll
    for (int c = 0; c < 64; c++) acc[c] = 0;

    // prologue: fill STAGES-1 stages
#pragma unroll
    for (int s = 0; s < STAGES - 1; s++) {
        uint32_t base = data + s * STAGE_BYTES;
        int ko = s * 128;
#pragma unroll
        for (int j = 0; j < 2; j++) cp16(base + soff[j], gA + goff[j] + ko);
#pragma unroll
        for (int j = 0; j < 2; j++) cp16(base + A_BYTES + soff[j], gB + goff[j] + ko);
        asm volatile("cp.async.commit_group;" ::: "memory");
    }

    for (int i = 0; i < NCHUNK; i++) {
        asm volatile("cp.async.wait_group %0;" :: "n"(STAGES - 2) : "memory");
        __syncthreads();

        int nj = i + STAGES - 1;
        if (nj < NCHUNK) {
            uint32_t wbase = data + (nj % STAGES) * STAGE_BYTES;
            int ko = nj * 128;
#pragma unroll
            for (int j = 0; j < 2; j++) cp16(wbase + soff[j], gA + goff[j] + ko);
#pragma unroll
            for (int j = 0; j < 2; j++) cp16(wbase + A_BYTES + soff[j], gB + goff[j] + ko);
        }
        asm volatile("cp.async.commit_group;" ::: "memory");

        uint32_t baseA = data + (i % STAGES) * STAGE_BYTES;
        uint32_t baseB = baseA + A_BYTES;

        if (is_imma) {
            // k bytes [0,64): 2 k-steps of m16n8k32
#pragma unroll
            for (int k = 0; k < 2; k++) {
                uint32_t afr[2][4];
#pragma unroll
                for (int mt = 0; mt < 2; mt++) {
                    uint32_t col = (uint32_t)(2 * k + a_khalf) ^ a_rowx[mt];
                    ldsm_x4(afr[mt], baseA + a_rowoff[mt] + (col << 4));
                }
#pragma unroll
                for (int np = 0; np < 4; np++) {
                    uint32_t bfr[4];
                    uint32_t col = (uint32_t)(2 * k + b_khalf) ^ b_rowx[np];
                    ldsm_x4(bfr, baseB + b_rowoff[np] + (col << 4));
#pragma unroll
                    for (int mt = 0; mt < 2; mt++) {
                        imma(&acc[(mt * 8 + np * 2 + 0) * 4], afr[mt], bfr + 0);
                        imma(&acc[(mt * 8 + np * 2 + 1) * 4], afr[mt], bfr + 2);
                    }
                }
            }
        } else {
            // k bytes [64,128): 4 column-blocks of 16B, lds128-vectorized dp4a
#pragma unroll
            for (int cb = 0; cb < 4; cb++) {
                uint32_t c16 = (uint32_t)(4 + cb);
                uint32_t colB  = (c16 ^ (uint32_t)lg) << 4;
                uint32_t colA0 = (c16 ^ (uint32_t)la) << 4;
                uint32_t colA1 = (c16 ^ (uint32_t)(la + 4)) << 4;
#pragma unroll
                for (int jjh = 0; jjh < 2; jjh++) {
                    int4 breg[4];
#pragma unroll
                    for (int j2 = 0; j2 < 4; j2++) {
                        int r = warpN * 64 + lg + 8 * (jjh * 4 + j2);
                        breg[j2] = lds128v(baseB + (uint32_t)(r * 128) + colB);
                    }
#pragma unroll
                    for (int par = 0; par < 2; par++) {
                        uint32_t colA = par ? colA1 : colA0;
                        int4 areg[4];
#pragma unroll
                        for (int t2 = 0; t2 < 4; t2++) {
                            int r = warpM * 32 + la + 4 * (par + 2 * t2);
                            areg[t2] = lds128v(baseA + (uint32_t)(r * 128) + colA);
                        }
#pragma unroll
                        for (int t2 = 0; t2 < 4; t2++) {
                            int ii = par + 2 * t2;
#pragma unroll
                            for (int j2 = 0; j2 < 4; j2++) {
                                int jj = jjh * 4 + j2;
                                int* a = &acc[ii * 8 + jj];
                                *a = __dp4a(areg[t2].x, breg[j2].x, *a);
                                *a = __dp4a(areg[t2].y, breg[j2].y, *a);
                                *a = __dp4a(areg[t2].z, breg[j2].z, *a);
                                *a = __dp4a(areg[t2].w, breg[j2].w, *a);
                            }
                        }
                    }
                }
            }
        }
    }

    // combine dp4a partials into imma warps, then dequant epilogue
    __syncthreads();
    int* buf = reinterpret_cast<int*>(dsm);    // 64KB, reuses pipeline stages
    if (!is_imma) {
#pragma unroll
        for (int ii = 0; ii < 8; ii++) {
            int rl = warpM * 32 + la + 4 * ii;
#pragma unroll
            for (int jj = 0; jj < 8; jj++)
                buf[rl * 128 + warpN * 64 + lg + 8 * jj] = acc[ii * 8 + jj];
        }
    }
    __syncthreads();

    if (is_imma) {
        float comb = g_scalars[4];
        float shc  = g_scalars[5];
#pragma unroll
        for (int mt = 0; mt < 2; mt++) {
            int r0l = warpM * 32 + mt * 16 + (lid >> 2);
            int r1l = r0l + 8;
            int r0 = m0 + r0l, r1 = m0 + r1l;
            float sh0 = shc * g_wrsum[r0];
            float sh1 = shc * g_wrsum[r1];
#pragma unroll
            for (int nt = 0; nt < 8; nt++) {
                int cl = warpN * 64 + nt * 8 + (lid & 3) * 2;
                int col = n0 + cl;
                float b0 = bias[col], b1 = bias[col + 1];
                int2 p0 = *reinterpret_cast<int2*>(buf + r0l * 128 + cl);
                int2 p1 = *reinterpret_cast<int2*>(buf + r1l * 128 + cl);
                const int* ac = &acc[(mt * 8 + nt) * 4];
                float2 o0, o1;
                o0.x = ((float)(ac[0] + p0.x) + b0) * comb + sh0;
                o0.y = ((float)(ac[1] + p0.y) + b1) * comb + sh0;
                o1.x = ((float)(ac[2] + p1.x) + b0) * comb + sh1;
                o1.y = ((float)(ac[3] + p1.y) + b1) * comb + sh1;
                *reinterpret_cast<float2*>(out + (size_t)r0 * DIM + col) = o0;
                *reinterpret_cast<float2*>(out + (size_t)r1 * DIM + col) = o1;
            }
        }
    }
}

// ---------------- launch ----------------
extern "C" void kernel_launch(void* const* d_in, const int* in_sizes, int n_in,
                              void* d_out, int out_size) {
    const float* x    = (const float*)d_in[0];
    const float* wt   = (const float*)d_in[1];
    const float* bias = (const float*)d_in[2];
    float* out = (float*)d_out;

    cudaFuncSetAttribute(k_gemm, cudaFuncAttributeMaxDynamicSharedMemorySize, GSMEM);

    k_reduce_x<<<1024, 256>>>(x);
    k_row_w<<<4096, 128>>>(wt);
    k_scalars<<<1, 256>>>();
    k_quant<<<4096, 256>>>(x, wt);
    dim3 grid(DIM / 128, DIM / 128);
    k_gemm<<<grid, NTHREADS, GSMEM>>>(bias, out);
}